// round 15
// baseline (speedup 1.0000x reference)
#include <cuda_runtime.h>
#include <cuda_bf16.h>
#include <cstdint>

#define NEG 0.01f
__device__ __forceinline__ float lrelu(float v) { return v >= 0.f ? v : NEG * v; }

// ---- bf16 GEMM tile: CTA 64(M) x 128(N) x 128(K) per iter, 2-stage smem ring ----
#define XS_STRIDE 136           // bf16 (128 + 8 pad) -> 272B rows, LDSM conflict-free
#define WS_STRIDE 136
#define XS_ELEMS (64 * XS_STRIDE)      // 8704
#define WS_ELEMS (128 * WS_STRIDE)     // 17408
#define STAGE_ELEMS (XS_ELEMS + WS_ELEMS)          // 26112 bf16 = 52224 B
#define NSTAGE 2
#define GEMM_SMEM_BYTES (NSTAGE * STAGE_ELEMS * 2) // 104448 B

// ---------------- scratch (device globals) ----------------
__device__ float g_P[2457600];                 // split-K partials
__device__ __nv_bfloat16 g_Xin[64 * 25600];
__device__ __nv_bfloat16 g_Xb1[64 * 3200];
__device__ __nv_bfloat16 g_Xb2[64 * 6400];
__device__ __nv_bfloat16 g_Xb3[64 * 12800];
__device__ __nv_bfloat16 g_X2b[64 * 50 * 128];
__device__ float g_H [64 * 50 * 128];
__device__ float g_PL[64 * 128];

// ---------------- helpers ----------------
__device__ __forceinline__ uint32_t pack_bf16(float lo, float hi) {
    uint32_t r;
    asm("cvt.rn.bf16x2.f32 %0, %1, %2;" : "=r"(r) : "f"(hi), "f"(lo));
    return r;
}
__device__ __forceinline__ void cp16(void* dst_smem, const void* src) {
    uint32_t d = (uint32_t)__cvta_generic_to_shared(dst_smem);
    asm volatile("cp.async.cg.shared.global [%0], [%1], 16;\n" :: "r"(d), "l"(src));
}
__device__ __forceinline__ void cp_commit() { asm volatile("cp.async.commit_group;\n"); }
template<int NN> __device__ __forceinline__ void cp_wait() {
    asm volatile("cp.async.wait_group %0;\n" :: "n"(NN));
}
__device__ __forceinline__ void ldsm4(uint32_t* r, uint32_t addr) {
    asm volatile("ldmatrix.sync.aligned.m8n8.x4.shared.b16 {%0,%1,%2,%3}, [%4];"
                 : "=r"(r[0]), "=r"(r[1]), "=r"(r[2]), "=r"(r[3]) : "r"(addr));
}
__device__ __forceinline__ void ldsm4t(uint32_t* r, uint32_t addr) {
    asm volatile("ldmatrix.sync.aligned.m8n8.x4.trans.shared.b16 {%0,%1,%2,%3}, [%4];"
                 : "=r"(r[0]), "=r"(r[1]), "=r"(r[2]), "=r"(r[3]) : "r"(addr));
}
__device__ __forceinline__ void mma16816(float* c, const uint32_t* a, uint32_t b0, uint32_t b1) {
    asm("mma.sync.aligned.m16n8k16.row.col.f32.bf16.bf16.f32 "
        "{%0,%1,%2,%3}, {%4,%5,%6,%7}, {%8,%9}, {%0,%1,%2,%3};"
        : "+f"(c[0]), "+f"(c[1]), "+f"(c[2]), "+f"(c[3])
        : "r"(a[0]), "r"(a[1]), "r"(a[2]), "r"(a[3]), "r"(b0), "r"(b1));
}

// ---------------- prep: convert input b -> bf16 ----------------
__global__ void prep_kernel(const float4* __restrict__ bin, uint2* __restrict__ Xin) {
    int i = blockIdx.x * 256 + threadIdx.x;
    if (i < 409600) {
        float4 v = bin[i];
        Xin[i] = make_uint2(pack_bf16(v.x, v.y), pack_bf16(v.z, v.w));
    }
}

// ---------------- reduce: sum split-K partials + bias (+leaky) -> bf16 ----------------
__global__ void reduce_act(const float4* __restrict__ P, const float4* __restrict__ bias,
                           uint2* __restrict__ Xb, int n4row, int total4, int nchunks, int leak) {
    int i = blockIdx.x * 256 + threadIdx.x;
    if (i < total4) {
        float4 s = P[i];
        for (int c = 1; c < nchunks; c++) {
            float4 p = P[i + (size_t)c * total4];
            s.x += p.x; s.y += p.y; s.z += p.z; s.w += p.w;
        }
        float4 b = bias[i % n4row];
        s.x += b.x; s.y += b.y; s.z += b.z; s.w += b.w;
        if (leak) { s.x = lrelu(s.x); s.y = lrelu(s.y); s.z = lrelu(s.z); s.w = lrelu(s.w); }
        Xb[i] = make_uint2(pack_bf16(s.x, s.y), pack_bf16(s.z, s.w));
    }
}

// ---------------- bf16 mma GEMM: BK=128, 2-stage ring, quarter-staged W ----------------
// X bf16 via cp.async (distance = 1 full 128-K iter); W fp32 LDG(.cs) -> bf16 STS
// in four 32-row quarters with 2 ping-pong reg buffers (LDG->STS = 1 quarter).
// grid: (N/128, numKChunks, M/64). direct=1: plain store (grid.y==1).
// direct=0: store partials at [blockIdx.y][64][N] (grid.z==1).
// K, chunkLen multiples of 128; N multiple of 128.
__global__ __launch_bounds__(256, 2) void gemm_bf16(
    const __nv_bfloat16* __restrict__ X, const float* __restrict__ W,
    float* __restrict__ Y, int K, int N, int chunkLen, int direct)
{
    extern __shared__ __align__(16) char smraw[];
    __nv_bfloat16* sm = reinterpret_cast<__nv_bfloat16*>(smraw);

    const int tid = threadIdx.x;
    const int warp = tid >> 5, lane = tid & 31;
    const int g = lane >> 2, t = lane & 3;

    const int n0 = blockIdx.x * 128;
    const int m0 = blockIdx.z * 64;
    const int k0 = blockIdx.y * chunkLen;
    int kend = k0 + chunkLen; if (kend > K) kend = K;
    const int iters = (kend - k0) >> 7;

    const int wm = (warp >> 2) * 32;     // 2(m) x 4(n) warps, 32x32 each
    const int wn = (warp & 3) * 32;

    float acc[2][4][4];
    #pragma unroll
    for (int i = 0; i < 2; i++)
        #pragma unroll
        for (int j = 0; j < 4; j++)
            #pragma unroll
            for (int r = 0; r < 4; r++) acc[i][j][r] = 0.f;

    // X staging (cp.async bf16): 4 threads/row, 4x16B each -> 256B/row, 64 rows
    const int xrow = tid >> 2, xseg = tid & 3;
    const __nv_bfloat16* Xg = X + (size_t)(m0 + xrow) * K + k0 + xseg * 8;

    // W quarter staging: quarter = 32 k-rows x 128 cols fp32. 8 threads/row, 4 float4.
    const int hrow = tid >> 3, hseg = tid & 7;
    const float* Wg = W + (size_t)(k0 + hrow) * N + n0 + hseg * 4;

    auto prefetchX = [&](int stage, int i) {
        __nv_bfloat16* Xs = sm + stage * STAGE_ELEMS;
        const __nv_bfloat16* src = Xg + i * 128;
        #pragma unroll
        for (int j = 0; j < 4; j++)
            cp16(Xs + xrow * XS_STRIDE + xseg * 8 + j * 32, src + j * 32);
    };

    float4 buf[2][4];
    auto ldgW_q = [&](int i, int q, int p) {
        const float* wp = Wg + (size_t)(i * 128 + q * 32) * N;
        #pragma unroll
        for (int j = 0; j < 4; j++)
            buf[p][j] = __ldcs(reinterpret_cast<const float4*>(wp + j * 32));
    };
    auto stsW_q = [&](int stage, int q, int p) {
        __nv_bfloat16* Ws = sm + stage * STAGE_ELEMS + XS_ELEMS
                          + (q * 32 + hrow) * WS_STRIDE + hseg * 4;
        #pragma unroll
        for (int j = 0; j < 4; j++) {
            float4 v = buf[p][j];
            *reinterpret_cast<uint2*>(Ws + j * 32)
                = make_uint2(pack_bf16(v.x, v.y), pack_bf16(v.z, v.w));
        }
    };

    const int a_row = wm + (lane & 15);
    const int a_col = (lane >> 4) * 8;
    const int b_row = (lane & 7) + ((lane >> 3) & 1) * 8;
    const int b_col = wn + (lane >> 4) * 8;

    auto compute_q = [&](int stage, int q) {
        const __nv_bfloat16* Xs = sm + stage * STAGE_ELEMS;
        const __nv_bfloat16* Ws = Xs + XS_ELEMS;
        uint32_t a0 = (uint32_t)__cvta_generic_to_shared(Xs + a_row * XS_STRIDE + a_col);
        uint32_t a1 = a0 + 16 * XS_STRIDE * 2;
        uint32_t b0a = (uint32_t)__cvta_generic_to_shared(Ws + b_row * WS_STRIDE + b_col);
        uint32_t b1a = b0a + 16 * 2;
        #pragma unroll
        for (int s = 2 * q; s < 2 * q + 2; s++) {   // s = k16 step, 0..7
            uint32_t A0[4], A1[4], B0[4], B1[4];
            ldsm4 (A0, a0  + s * 32);
            ldsm4 (A1, a1  + s * 32);
            ldsm4t(B0, b0a + s * 16 * WS_STRIDE * 2);
            ldsm4t(B1, b1a + s * 16 * WS_STRIDE * 2);
            mma16816(acc[0][0], A0, B0[0], B0[1]);
            mma16816(acc[0][1], A0, B0[2], B0[3]);
            mma16816(acc[0][2], A0, B1[0], B1[1]);
            mma16816(acc[0][3], A0, B1[2], B1[3]);
            mma16816(acc[1][0], A1, B0[0], B0[1]);
            mma16816(acc[1][1], A1, B0[2], B0[3]);
            mma16816(acc[1][2], A1, B1[0], B1[1]);
            mma16816(acc[1][3], A1, B1[2], B1[3]);
        }
    };

    // ---- prologue: X(0) in flight; W(0) staged (overlapped ldg/sts); W(1,q0) in regs ----
    prefetchX(0, 0); cp_commit();
    ldgW_q(0, 0, 0); ldgW_q(0, 1, 1);
    stsW_q(0, 0, 0); ldgW_q(0, 2, 0);
    stsW_q(0, 1, 1); ldgW_q(0, 3, 1);
    stsW_q(0, 2, 0); stsW_q(0, 3, 1);
    if (iters > 1) ldgW_q(1, 0, 0);
    cp_wait<0>(); __syncthreads();

    // ---- mainloop: 1 sync per 128-K iter ----
    for (int i = 0; i < iters; i++) {
        const int si = i & 1, s1 = si ^ 1;
        const bool nxt = (i + 1 < iters), nxt2 = (i + 2 < iters);
        if (nxt) prefetchX(s1, i + 1);
        cp_commit();

        if (nxt) stsW_q(s1, 0, 0);          // W(i+1,q0), loaded last quarter
        if (nxt) ldgW_q(i + 1, 1, 1);
        compute_q(si, 0);

        if (nxt) stsW_q(s1, 1, 1);
        if (nxt) ldgW_q(i + 1, 2, 0);
        compute_q(si, 1);

        if (nxt) stsW_q(s1, 2, 0);
        if (nxt) ldgW_q(i + 1, 3, 1);
        compute_q(si, 2);

        if (nxt) stsW_q(s1, 3, 1);
        if (nxt2) ldgW_q(i + 2, 0, 0);
        compute_q(si, 3);

        cp_wait<0>(); __syncthreads();
    }

    // ---- epilogue ----
    if (direct) {
        #pragma unroll
        for (int mt = 0; mt < 2; mt++) {
            int r = m0 + wm + mt * 16 + g;
            #pragma unroll
            for (int nt = 0; nt < 4; nt++) {
                int c = n0 + wn + nt * 8 + 2 * t;
                Y[(size_t)r * N + c]           = acc[mt][nt][0];
                Y[(size_t)r * N + c + 1]       = acc[mt][nt][1];
                Y[(size_t)(r + 8) * N + c]     = acc[mt][nt][2];
                Y[(size_t)(r + 8) * N + c + 1] = acc[mt][nt][3];
            }
        }
    } else {
        float* P = Y + (size_t)blockIdx.y * 64 * N;
        #pragma unroll
        for (int mt = 0; mt < 2; mt++) {
            int r = wm + mt * 16 + g;
            #pragma unroll
            for (int nt = 0; nt < 4; nt++) {
                int c = n0 + wn + nt * 8 + 2 * t;
                *reinterpret_cast<float2*>(&P[(size_t)r * N + c])
                    = make_float2(acc[mt][nt][0], acc[mt][nt][1]);
                *reinterpret_cast<float2*>(&P[(size_t)(r + 8) * N + c])
                    = make_float2(acc[mt][nt][2], acc[mt][nt][3]);
            }
        }
    }
}

// ---------------- GCN aggregation (per-sample CTA), bf16 feature out ----------------
__global__ __launch_bounds__(256) void gcn_agg(
    const float* __restrict__ H, const int* __restrict__ ei,
    const float* __restrict__ bias, __nv_bfloat16* __restrict__ Xout,
    float* __restrict__ pooled)
{
    __shared__ int   s_src[450];
    __shared__ float s_norm[450];
    __shared__ int   s_cnt[50], s_start[50], s_cur[50];
    __shared__ float s_dinv[50];
    __shared__ float s_pool[128];

    const int b = blockIdx.x, tid = threadIdx.x;
    const int* eb = ei + (size_t)b * 800;

    if (tid < 50)  s_cnt[tid] = 0;
    if (tid < 128) s_pool[tid] = 0.f;
    __syncthreads();

    for (int e = tid; e < 450; e += 256) {
        int dst = (e < 400) ? eb[400 + e] : (e - 400);
        atomicAdd(&s_cnt[dst], 1);
    }
    __syncthreads();

    if (tid < 50) s_dinv[tid] = rsqrtf((float)s_cnt[tid]);
    if (tid == 0) {
        int s = 0;
        for (int i = 0; i < 50; i++) { s_start[i] = s; s += s_cnt[i]; }
    }
    __syncthreads();
    if (tid < 50) s_cur[tid] = s_start[tid];
    __syncthreads();

    for (int e = tid; e < 450; e += 256) {
        int src, dst;
        if (e < 400) { src = eb[e]; dst = eb[400 + e]; }
        else         { src = dst = e - 400; }
        int pos = atomicAdd(&s_cur[dst], 1);
        s_src[pos]  = src;
        s_norm[pos] = s_dinv[src] * s_dinv[dst];
    }
    __syncthreads();

    const int f  = tid & 127;
    const int n0 = tid >> 7;
    const float* Hb = H + (size_t)b * 50 * 128;
    float pp = 0.f;
    for (int n = n0; n < 50; n += 2) {
        float acc = 0.f;
        int st = s_start[n], en = st + s_cnt[n];
        for (int j = st; j < en; j++)
            acc += s_norm[j] * Hb[s_src[j] * 128 + f];
        float v = lrelu(acc + bias[f]);
        if (Xout) Xout[(size_t)(b * 50 + n) * 128 + f] = __float2bfloat16(v);
        pp += v;
    }
    if (pooled) {
        atomicAdd(&s_pool[f], pp);
        __syncthreads();
        if (tid < 128) pooled[b * 128 + tid] = s_pool[tid] * (1.0f / 50.0f);
    }
}

// ---------------- head: FC1 -> FC2 -> cumsum (warp scan) -> sigmoid ----------------
__global__ __launch_bounds__(256) void head_kernel(
    const float* __restrict__ pooled,
    const float* __restrict__ Wf1, const float* __restrict__ bf1,
    const float* __restrict__ Wf2, const float* __restrict__ bf2,
    float* __restrict__ out)
{
    __shared__ float s_p[128];
    __shared__ float s_z1[64];
    __shared__ float s_z2[2000];

    const int b = blockIdx.x, tid = threadIdx.x;
    if (tid < 128) s_p[tid] = pooled[b * 128 + tid];
    __syncthreads();

    if (tid < 64) {
        float a = bf1[tid];
        #pragma unroll 8
        for (int k = 0; k < 128; k++) a += s_p[k] * Wf1[k * 64 + tid];
        s_z1[tid] = lrelu(a);
    }
    __syncthreads();

    for (int j = tid; j < 2000; j += 256) {
        float a = bf2[j];
        #pragma unroll
        for (int k = 0; k < 64; k++) a += s_z1[k] * Wf2[k * 2000 + j];
        s_z2[j] = a;
    }
    __syncthreads();

    if (tid < 64) {
        int c = tid >> 5, l = tid & 31;
        int k0 = l * 32, k1 = (k0 + 32 < 1000) ? k0 + 32 : 1000;
        float s = 0.f;
        for (int k = k0; k < k1; k++) s += s_z2[2 * k + c];
        float run = s;
        #pragma unroll
        for (int d = 1; d < 32; d <<= 1) {
            float v = __shfl_up_sync(0xffffffff, run, d);
            if (l >= d) run += v;
        }
        float a = run - s;
        float* ob = out + (size_t)b * 2000;
        for (int k = k0; k < k1; k++) {
            a += s_z2[2 * k + c];
            ob[2 * k + c] = 1.f / (1.f + expf(-a));
        }
    }
}

// ---------------- launch ----------------
extern "C" void kernel_launch(void* const* d_in, const int* in_sizes, int n_in,
                              void* d_out, int out_size)
{
    const float* bin = (const float*)d_in[0];
    const int*   ei  = (const int*)  d_in[1];
    const float* W1  = (const float*)d_in[2];
    const float* b1  = (const float*)d_in[3];
    const float* W2  = (const float*)d_in[4];
    const float* b2  = (const float*)d_in[5];
    const float* W3  = (const float*)d_in[6];
    const float* b3  = (const float*)d_in[7];
    const float* Wc1 = (const float*)d_in[8];
    const float* bc1 = (const float*)d_in[9];
    const float* Wc2 = (const float*)d_in[10];
    const float* bc2 = (const float*)d_in[11];
    const float* Wf1 = (const float*)d_in[12];
    const float* bf1 = (const float*)d_in[13];
    const float* Wf2 = (const float*)d_in[14];
    const float* bf2 = (const float*)d_in[15];
    float* out = (float*)d_out;

    float *P, *H, *PL;
    __nv_bfloat16 *Xin, *Xb1, *Xb2, *Xb3, *X2b;
    cudaGetSymbolAddress((void**)&P,   g_P);
    cudaGetSymbolAddress((void**)&Xin, g_Xin);
    cudaGetSymbolAddress((void**)&Xb1, g_Xb1);
    cudaGetSymbolAddress((void**)&Xb2, g_Xb2);
    cudaGetSymbolAddress((void**)&Xb3, g_Xb3);
    cudaGetSymbolAddress((void**)&X2b, g_X2b);
    cudaGetSymbolAddress((void**)&H,   g_H);
    cudaGetSymbolAddress((void**)&PL,  g_PL);

    cudaFuncSetAttribute(gemm_bf16, cudaFuncAttributeMaxDynamicSharedMemorySize,
                         GEMM_SMEM_BYTES);

    // prep: convert input to bf16
    prep_kernel<<<1600, 256>>>((const float4*)bin, (uint2*)Xin);

    // encoder L1: (64,25600)@(25600,3200); 12 K-chunks of 2176 (17 iters, last 13)
    gemm_bf16<<<dim3(25, 12, 1), 256, GEMM_SMEM_BYTES>>>(Xin, W1, P, 25600, 3200, 2176, 0);
    reduce_act<<<200, 256>>>((const float4*)P, (const float4*)b1, (uint2*)Xb1, 800, 51200, 12, 1);

    // encoder L2: (64,3200)@(3200,6400); 5 K-chunks of 640 (5 iters) -> 250 CTAs
    gemm_bf16<<<dim3(50, 5, 1), 256, GEMM_SMEM_BYTES>>>(Xb1, W2, P, 3200, 6400, 640, 0);
    reduce_act<<<400, 256>>>((const float4*)P, (const float4*)b2, (uint2*)Xb2, 1600, 102400, 5, 1);

    // encoder L3 (no act): (64,6400)@(6400,12800); 3 K-chunks of 2176 (17/17/16 iters)
    gemm_bf16<<<dim3(100, 3, 1), 256, GEMM_SMEM_BYTES>>>(Xb2, W3, P, 6400, 12800, 2176, 0);
    reduce_act<<<800, 256>>>((const float4*)P, (const float4*)b3, (uint2*)Xb3, 3200, 204800, 3, 0);

    // GCN L1: H = nodes(3200,256)@Wc1(256,128), direct store (2 iters)
    gemm_bf16<<<dim3(1, 1, 50), 256, GEMM_SMEM_BYTES>>>(Xb3, Wc1, H, 256, 128, 256, 1);
    gcn_agg<<<64, 256>>>(H, ei, bc1, X2b, nullptr);

    // GCN L2: H = X2(3200,128)@Wc2(128,128), direct store (1 iter)
    gemm_bf16<<<dim3(1, 1, 50), 256, GEMM_SMEM_BYTES>>>(X2b, Wc2, H, 128, 128, 128, 1);
    gcn_agg<<<64, 256>>>(H, ei, bc2, nullptr, PL);

    head_kernel<<<64, 256>>>(PL, Wf1, bf1, Wf2, bf2, out);
}

// round 16
// speedup vs baseline: 1.3204x; 1.3204x over previous
#include <cuda_runtime.h>
#include <cuda_bf16.h>
#include <cstdint>

#define NEG 0.01f
__device__ __forceinline__ float lrelu(float v) { return v >= 0.f ? v : NEG * v; }

// ---- bf16 GEMM tile: CTA 64(M) x 128(N) x 64(K) per iter, 3-stage smem ring ----
#define XS_STRIDE 72            // bf16 (64 + 8 pad) -> 144B rows, LDSM conflict-free
#define WS_STRIDE 136           // bf16 (128 + 8 pad) -> 272B rows
#define XS_ELEMS (64 * XS_STRIDE)
#define WS_ELEMS (64 * WS_STRIDE)
#define STAGE_ELEMS (XS_ELEMS + WS_ELEMS)          // 13312 bf16
#define NSTAGE 3
#define GEMM_SMEM_BYTES (NSTAGE * STAGE_ELEMS * 2) // 79872 B
#define HS_STRIDE 132

// ---------------- scratch (device globals) ----------------
__device__ float g_P[2457600];                 // split-K partials
__device__ __nv_bfloat16 g_Xin[64 * 25600];
__device__ __nv_bfloat16 g_Xb1[64 * 3200];
__device__ __nv_bfloat16 g_Xb2[64 * 6400];
__device__ __nv_bfloat16 g_Xb3[64 * 12800 + 4096];   // padded: fused GCN M-tile over-read
__device__ __nv_bfloat16 g_X2b[64 * 50 * 128 + 4096];
__device__ float g_PL[64 * 128];

// ---------------- helpers ----------------
__device__ __forceinline__ uint32_t pack_bf16(float lo, float hi) {
    uint32_t r;
    asm("cvt.rn.bf16x2.f32 %0, %1, %2;" : "=r"(r) : "f"(hi), "f"(lo));
    return r;
}
__device__ __forceinline__ void cp16(void* dst_smem, const void* src) {
    uint32_t d = (uint32_t)__cvta_generic_to_shared(dst_smem);
    asm volatile("cp.async.cg.shared.global [%0], [%1], 16;\n" :: "r"(d), "l"(src));
}
__device__ __forceinline__ void cp_commit() { asm volatile("cp.async.commit_group;\n"); }
template<int NN> __device__ __forceinline__ void cp_wait() {
    asm volatile("cp.async.wait_group %0;\n" :: "n"(NN));
}
__device__ __forceinline__ void ldsm4(uint32_t* r, uint32_t addr) {
    asm volatile("ldmatrix.sync.aligned.m8n8.x4.shared.b16 {%0,%1,%2,%3}, [%4];"
                 : "=r"(r[0]), "=r"(r[1]), "=r"(r[2]), "=r"(r[3]) : "r"(addr));
}
__device__ __forceinline__ void ldsm4t(uint32_t* r, uint32_t addr) {
    asm volatile("ldmatrix.sync.aligned.m8n8.x4.trans.shared.b16 {%0,%1,%2,%3}, [%4];"
                 : "=r"(r[0]), "=r"(r[1]), "=r"(r[2]), "=r"(r[3]) : "r"(addr));
}
__device__ __forceinline__ void mma16816(float* c, const uint32_t* a, uint32_t b0, uint32_t b1) {
    asm("mma.sync.aligned.m16n8k16.row.col.f32.bf16.bf16.f32 "
        "{%0,%1,%2,%3}, {%4,%5,%6,%7}, {%8,%9}, {%0,%1,%2,%3};"
        : "+f"(c[0]), "+f"(c[1]), "+f"(c[2]), "+f"(c[3])
        : "r"(a[0]), "r"(a[1]), "r"(a[2]), "r"(a[3]), "r"(b0), "r"(b1));
}

// ---------------- prep: convert input b -> bf16 ----------------
__global__ void prep_kernel(const float4* __restrict__ bin, uint2* __restrict__ Xin) {
    int i = blockIdx.x * 256 + threadIdx.x;
    if (i < 409600) {
        float4 v = bin[i];
        Xin[i] = make_uint2(pack_bf16(v.x, v.y), pack_bf16(v.z, v.w));
    }
}

// ---------------- reduce: sum split-K partials + bias (+leaky) -> bf16 ----------------
__global__ void reduce_act(const float4* __restrict__ P, const float4* __restrict__ bias,
                           uint2* __restrict__ Xb, int n4row, int total4, int nchunks, int leak) {
    int i = blockIdx.x * 256 + threadIdx.x;
    if (i < total4) {
        float4 s = P[i];
        for (int c = 1; c < nchunks; c++) {
            float4 p = P[i + (size_t)c * total4];
            s.x += p.x; s.y += p.y; s.z += p.z; s.w += p.w;
        }
        float4 b = bias[i % n4row];
        s.x += b.x; s.y += b.y; s.z += b.z; s.w += b.w;
        if (leak) { s.x = lrelu(s.x); s.y = lrelu(s.y); s.z = lrelu(s.z); s.w = lrelu(s.w); }
        Xb[i] = make_uint2(pack_bf16(s.x, s.y), pack_bf16(s.z, s.w));
    }
}

// ---------------- bf16 mma GEMM (R14 proven structure; split-K partial epilogue) ----------------
// X bf16 via cp.async (3-stage ring, distance 2); W fp32 LDG(.cs) -> bf16 STS with
// 2 half-K register buffers: LDG->STS distance = 1 full iteration.
// grid: (N/128, numKChunks, 1). Stores partials at [blockIdx.y][64][N].
// K, chunkLen multiples of 64; N multiple of 128.
__global__ __launch_bounds__(256, 2) void gemm_bf16(
    const __nv_bfloat16* __restrict__ X, const float* __restrict__ W,
    float* __restrict__ Y, int K, int N, int chunkLen)
{
    extern __shared__ __align__(16) char smraw[];
    __nv_bfloat16* sm = reinterpret_cast<__nv_bfloat16*>(smraw);

    const int tid = threadIdx.x;
    const int warp = tid >> 5, lane = tid & 31;
    const int g = lane >> 2, t = lane & 3;

    const int n0 = blockIdx.x * 128;
    const int k0 = blockIdx.y * chunkLen;
    int kend = k0 + chunkLen; if (kend > K) kend = K;
    const int iters = (kend - k0) >> 6;

    const int wm = (warp >> 2) * 32;
    const int wn = (warp & 3) * 32;

    float acc[2][4][4];
    #pragma unroll
    for (int i = 0; i < 2; i++)
        #pragma unroll
        for (int j = 0; j < 4; j++)
            #pragma unroll
            for (int r = 0; r < 4; r++) acc[i][j][r] = 0.f;

    const int xrow = tid >> 3, xseg = tid & 7;
    const __nv_bfloat16* Xg = X + (size_t)xrow * K + k0 + xseg * 8;

    const int hrow = tid >> 3, hseg = tid & 7;
    const float* Wg = W + (size_t)(k0 + hrow) * N + n0 + hseg * 4;

    auto prefetchX = [&](int stage, int i) {
        __nv_bfloat16* Xs = sm + stage * STAGE_ELEMS;
        const __nv_bfloat16* src = Xg + i * 64;
        cp16(Xs + xrow * XS_STRIDE + xseg * 8,        src);
        cp16(Xs + (xrow + 32) * XS_STRIDE + xseg * 8, src + (size_t)32 * K);
    };

    float4 buf[2][4];
    auto ldgW_half = [&](int i, int h, int p) {
        const float* wp = Wg + (size_t)(i * 64 + h * 32) * N;
        #pragma unroll
        for (int j = 0; j < 4; j++)
            buf[p][j] = __ldcs(reinterpret_cast<const float4*>(wp + j * 32));
    };
    auto stsW_half = [&](int stage, int h, int p) {
        __nv_bfloat16* Ws = sm + stage * STAGE_ELEMS + XS_ELEMS
                          + (h * 32 + hrow) * WS_STRIDE + hseg * 4;
        #pragma unroll
        for (int j = 0; j < 4; j++) {
            float4 v = buf[p][j];
            *reinterpret_cast<uint2*>(Ws + j * 32)
                = make_uint2(pack_bf16(v.x, v.y), pack_bf16(v.z, v.w));
        }
    };

    const int a_row = wm + (lane & 15);
    const int a_col = (lane >> 4) * 8;
    const int b_row = (lane & 7) + ((lane >> 3) & 1) * 8;
    const int b_col = wn + (lane >> 4) * 8;

    auto compute_half = [&](int stage, int h) {
        const __nv_bfloat16* Xs = sm + stage * STAGE_ELEMS;
        const __nv_bfloat16* Ws = Xs + XS_ELEMS;
        uint32_t a0 = (uint32_t)__cvta_generic_to_shared(Xs + a_row * XS_STRIDE + a_col);
        uint32_t a1 = a0 + 16 * XS_STRIDE * 2;
        uint32_t b0a = (uint32_t)__cvta_generic_to_shared(Ws + b_row * WS_STRIDE + b_col);
        uint32_t b1a = b0a + 16 * 2;
        #pragma unroll
        for (int s = 2 * h; s < 2 * h + 2; s++) {
            uint32_t A0[4], A1[4], B0[4], B1[4];
            ldsm4 (A0, a0  + s * 32);
            ldsm4 (A1, a1  + s * 32);
            ldsm4t(B0, b0a + s * 16 * WS_STRIDE * 2);
            ldsm4t(B1, b1a + s * 16 * WS_STRIDE * 2);
            mma16816(acc[0][0], A0, B0[0], B0[1]);
            mma16816(acc[0][1], A0, B0[2], B0[3]);
            mma16816(acc[0][2], A0, B1[0], B1[1]);
            mma16816(acc[0][3], A0, B1[2], B1[3]);
            mma16816(acc[1][0], A1, B0[0], B0[1]);
            mma16816(acc[1][1], A1, B0[2], B0[3]);
            mma16816(acc[1][2], A1, B1[0], B1[1]);
            mma16816(acc[1][3], A1, B1[2], B1[3]);
        }
    };

    prefetchX(0, 0); cp_commit();
    if (iters > 1) prefetchX(1, 1);
    cp_commit();
    ldgW_half(0, 0, 0); ldgW_half(0, 1, 1);
    stsW_half(0, 0, 0); stsW_half(0, 1, 1);
    if (iters > 1) { ldgW_half(1, 0, 0); ldgW_half(1, 1, 1); }
    cp_wait<1>(); __syncthreads();

    for (int i = 0; i < iters; i++) {
        if (i + 2 < iters) prefetchX((i + 2) % NSTAGE, i + 2);
        cp_commit();
        const int si = i % NSTAGE, s1 = (i + 1) % NSTAGE;

        if (i + 1 < iters) stsW_half(s1, 0, 0);
        if (i + 2 < iters) ldgW_half(i + 2, 0, 0);
        compute_half(si, 0);

        if (i + 1 < iters) stsW_half(s1, 1, 1);
        if (i + 2 < iters) ldgW_half(i + 2, 1, 1);
        compute_half(si, 1);

        cp_wait<1>(); __syncthreads();
    }

    // partial slab: [blockIdx.y][64][N]
    float* P = Y + (size_t)blockIdx.y * 64 * N;
    #pragma unroll
    for (int mt = 0; mt < 2; mt++) {
        int r = wm + mt * 16 + g;
        #pragma unroll
        for (int nt = 0; nt < 4; nt++) {
            int c = n0 + wn + nt * 8 + 2 * t;
            *reinterpret_cast<float2*>(&P[(size_t)r * N + c])
                = make_float2(acc[mt][nt][0], acc[mt][nt][1]);
            *reinterpret_cast<float2*>(&P[(size_t)(r + 8) * N + c])
                = make_float2(acc[mt][nt][2], acc[mt][nt][3]);
        }
    }
}

// ---------------- fused GCN layer: per-sample GEMM(50x128,K) + aggregation ----------------
// One CTA per sample. H = X[b*50:+50, :K] @ W[K,128] computed with the same mma
// mainloop into smem (rows 50..63 are padding, ignored), then CSR aggregation.
__global__ __launch_bounds__(256) void gcn_fused(
    const __nv_bfloat16* __restrict__ X, const float* __restrict__ W,
    const int* __restrict__ ei, const float* __restrict__ bias,
    __nv_bfloat16* __restrict__ Xout, float* __restrict__ pooled, int K)
{
    extern __shared__ __align__(16) char smraw[];
    __nv_bfloat16* sm = reinterpret_cast<__nv_bfloat16*>(smraw);
    __shared__ float Hs[64 * HS_STRIDE];
    __shared__ int   s_src[450];
    __shared__ float s_norm[450];
    __shared__ int   s_cnt[50], s_start[50], s_cur[50];
    __shared__ float s_dinv[50];
    __shared__ float s_pool[128];

    const int b = blockIdx.x, tid = threadIdx.x;
    const int warp = tid >> 5, lane = tid & 31;
    const int g = lane >> 2, t = lane & 3;
    const int* eb = ei + (size_t)b * 800;

    // ---- CSR build (independent of gemm smem) ----
    if (tid < 50)  s_cnt[tid] = 0;
    if (tid < 128) s_pool[tid] = 0.f;
    __syncthreads();
    for (int e = tid; e < 450; e += 256) {
        int dst = (e < 400) ? eb[400 + e] : (e - 400);
        atomicAdd(&s_cnt[dst], 1);
    }
    __syncthreads();
    if (tid < 50) s_dinv[tid] = rsqrtf((float)s_cnt[tid]);
    if (tid == 0) {
        int s = 0;
        for (int i = 0; i < 50; i++) { s_start[i] = s; s += s_cnt[i]; }
    }
    __syncthreads();
    if (tid < 50) s_cur[tid] = s_start[tid];
    __syncthreads();
    for (int e = tid; e < 450; e += 256) {
        int src, dst;
        if (e < 400) { src = eb[e]; dst = eb[400 + e]; }
        else         { src = dst = e - 400; }
        int pos = atomicAdd(&s_cur[dst], 1);
        s_src[pos]  = src;
        s_norm[pos] = s_dinv[src] * s_dinv[dst];
    }

    // ---- GEMM: rows b*50 .. b*50+63 (padded), N=128, iters = K/64 ----
    const int iters = K >> 6;
    const int wm = (warp >> 2) * 32;
    const int wn = (warp & 3) * 32;

    float acc[2][4][4];
    #pragma unroll
    for (int i = 0; i < 2; i++)
        #pragma unroll
        for (int j = 0; j < 4; j++)
            #pragma unroll
            for (int r = 0; r < 4; r++) acc[i][j][r] = 0.f;

    const int xrow = tid >> 3, xseg = tid & 7;
    const __nv_bfloat16* Xg = X + (size_t)(b * 50 + xrow) * K + xseg * 8;
    const int hrow = tid >> 3, hseg = tid & 7;
    const float* Wg = W + (size_t)hrow * 128 + hseg * 4;

    auto prefetchX = [&](int stage, int i) {
        __nv_bfloat16* Xs = sm + stage * STAGE_ELEMS;
        const __nv_bfloat16* src = Xg + i * 64;
        cp16(Xs + xrow * XS_STRIDE + xseg * 8,        src);
        cp16(Xs + (xrow + 32) * XS_STRIDE + xseg * 8, src + (size_t)32 * K);
    };
    float4 buf[2][4];
    auto ldgW_half = [&](int i, int h, int p) {
        const float* wp = Wg + (size_t)(i * 64 + h * 32) * 128;
        #pragma unroll
        for (int j = 0; j < 4; j++)
            buf[p][j] = *reinterpret_cast<const float4*>(wp + j * 32);
    };
    auto stsW_half = [&](int stage, int h, int p) {
        __nv_bfloat16* Ws = sm + stage * STAGE_ELEMS + XS_ELEMS
                          + (h * 32 + hrow) * WS_STRIDE + hseg * 4;
        #pragma unroll
        for (int j = 0; j < 4; j++) {
            float4 v = buf[p][j];
            *reinterpret_cast<uint2*>(Ws + j * 32)
                = make_uint2(pack_bf16(v.x, v.y), pack_bf16(v.z, v.w));
        }
    };
    const int a_row = wm + (lane & 15);
    const int a_col = (lane >> 4) * 8;
    const int b_row = (lane & 7) + ((lane >> 3) & 1) * 8;
    const int b_col = wn + (lane >> 4) * 8;
    auto compute_half = [&](int stage, int h) {
        const __nv_bfloat16* Xs = sm + stage * STAGE_ELEMS;
        const __nv_bfloat16* Ws = Xs + XS_ELEMS;
        uint32_t a0 = (uint32_t)__cvta_generic_to_shared(Xs + a_row * XS_STRIDE + a_col);
        uint32_t a1 = a0 + 16 * XS_STRIDE * 2;
        uint32_t b0a = (uint32_t)__cvta_generic_to_shared(Ws + b_row * WS_STRIDE + b_col);
        uint32_t b1a = b0a + 16 * 2;
        #pragma unroll
        for (int s = 2 * h; s < 2 * h + 2; s++) {
            uint32_t A0[4], A1[4], B0[4], B1[4];
            ldsm4 (A0, a0  + s * 32);
            ldsm4 (A1, a1  + s * 32);
            ldsm4t(B0, b0a + s * 16 * WS_STRIDE * 2);
            ldsm4t(B1, b1a + s * 16 * WS_STRIDE * 2);
            mma16816(acc[0][0], A0, B0[0], B0[1]);
            mma16816(acc[0][1], A0, B0[2], B0[3]);
            mma16816(acc[0][2], A0, B1[0], B1[1]);
            mma16816(acc[0][3], A0, B1[2], B1[3]);
            mma16816(acc[1][0], A1, B0[0], B0[1]);
            mma16816(acc[1][1], A1, B0[2], B0[3]);
            mma16816(acc[1][2], A1, B1[0], B1[1]);
            mma16816(acc[1][3], A1, B1[2], B1[3]);
        }
    };

    prefetchX(0, 0); cp_commit();
    if (iters > 1) prefetchX(1, 1);
    cp_commit();
    ldgW_half(0, 0, 0); ldgW_half(0, 1, 1);
    stsW_half(0, 0, 0); stsW_half(0, 1, 1);
    if (iters > 1) { ldgW_half(1, 0, 0); ldgW_half(1, 1, 1); }
    cp_wait<1>(); __syncthreads();

    for (int i = 0; i < iters; i++) {
        if (i + 2 < iters) prefetchX((i + 2) % NSTAGE, i + 2);
        cp_commit();
        const int si = i % NSTAGE, s1 = (i + 1) % NSTAGE;
        if (i + 1 < iters) stsW_half(s1, 0, 0);
        if (i + 2 < iters) ldgW_half(i + 2, 0, 0);
        compute_half(si, 0);
        if (i + 1 < iters) stsW_half(s1, 1, 1);
        if (i + 2 < iters) ldgW_half(i + 2, 1, 1);
        compute_half(si, 1);
        cp_wait<1>(); __syncthreads();
    }

    // epilogue -> smem H
    #pragma unroll
    for (int mt = 0; mt < 2; mt++) {
        int r = wm + mt * 16 + g;
        #pragma unroll
        for (int nt = 0; nt < 4; nt++) {
            int c = wn + nt * 8 + 2 * t;
            Hs[r * HS_STRIDE + c]           = acc[mt][nt][0];
            Hs[r * HS_STRIDE + c + 1]       = acc[mt][nt][1];
            Hs[(r + 8) * HS_STRIDE + c]     = acc[mt][nt][2];
            Hs[(r + 8) * HS_STRIDE + c + 1] = acc[mt][nt][3];
        }
    }
    __syncthreads();

    // ---- aggregation from smem H ----
    const int f  = tid & 127;
    const int n0 = tid >> 7;
    float pp = 0.f;
    for (int n = n0; n < 50; n += 2) {
        float a = 0.f;
        int st = s_start[n], en = st + s_cnt[n];
        for (int j = st; j < en; j++)
            a += s_norm[j] * Hs[s_src[j] * HS_STRIDE + f];
        float v = lrelu(a + bias[f]);
        if (Xout) Xout[(size_t)(b * 50 + n) * 128 + f] = __float2bfloat16(v);
        pp += v;
    }
    if (pooled) {
        atomicAdd(&s_pool[f], pp);
        __syncthreads();
        if (tid < 128) pooled[b * 128 + tid] = s_pool[tid] * (1.0f / 50.0f);
    }
}

// ---------------- head: FC1 -> FC2 -> cumsum (warp scan) -> sigmoid ----------------
__global__ __launch_bounds__(256) void head_kernel(
    const float* __restrict__ pooled,
    const float* __restrict__ Wf1, const float* __restrict__ bf1,
    const float* __restrict__ Wf2, const float* __restrict__ bf2,
    float* __restrict__ out)
{
    __shared__ float s_p[128];
    __shared__ float s_z1[64];
    __shared__ float s_z2[2000];

    const int b = blockIdx.x, tid = threadIdx.x;
    if (tid < 128) s_p[tid] = pooled[b * 128 + tid];
    __syncthreads();

    if (tid < 64) {
        float a = bf1[tid];
        #pragma unroll 8
        for (int k = 0; k < 128; k++) a += s_p[k] * Wf1[k * 64 + tid];
        s_z1[tid] = lrelu(a);
    }
    __syncthreads();

    for (int j = tid; j < 2000; j += 256) {
        float a = bf2[j];
        #pragma unroll
        for (int k = 0; k < 64; k++) a += s_z1[k] * Wf2[k * 2000 + j];
        s_z2[j] = a;
    }
    __syncthreads();

    if (tid < 64) {
        int c = tid >> 5, l = tid & 31;
        int k0 = l * 32, k1 = (k0 + 32 < 1000) ? k0 + 32 : 1000;
        float s = 0.f;
        for (int k = k0; k < k1; k++) s += s_z2[2 * k + c];
        float run = s;
        #pragma unroll
        for (int d = 1; d < 32; d <<= 1) {
            float v = __shfl_up_sync(0xffffffff, run, d);
            if (l >= d) run += v;
        }
        float a = run - s;
        float* ob = out + (size_t)b * 2000;
        for (int k = k0; k < k1; k++) {
            a += s_z2[2 * k + c];
            ob[2 * k + c] = 1.f / (1.f + expf(-a));
        }
    }
}

// ---------------- launch ----------------
extern "C" void kernel_launch(void* const* d_in, const int* in_sizes, int n_in,
                              void* d_out, int out_size)
{
    const float* bin = (const float*)d_in[0];
    const int*   ei  = (const int*)  d_in[1];
    const float* W1  = (const float*)d_in[2];
    const float* b1  = (const float*)d_in[3];
    const float* W2  = (const float*)d_in[4];
    const float* b2  = (const float*)d_in[5];
    const float* W3  = (const float*)d_in[6];
    const float* b3  = (const float*)d_in[7];
    const float* Wc1 = (const float*)d_in[8];
    const float* bc1 = (const float*)d_in[9];
    const float* Wc2 = (const float*)d_in[10];
    const float* bc2 = (const float*)d_in[11];
    const float* Wf1 = (const float*)d_in[12];
    const float* bf1 = (const float*)d_in[13];
    const float* Wf2 = (const float*)d_in[14];
    const float* bf2 = (const float*)d_in[15];
    float* out = (float*)d_out;

    float *P, *PL;
    __nv_bfloat16 *Xin, *Xb1, *Xb2, *Xb3, *X2b;
    cudaGetSymbolAddress((void**)&P,   g_P);
    cudaGetSymbolAddress((void**)&Xin, g_Xin);
    cudaGetSymbolAddress((void**)&Xb1, g_Xb1);
    cudaGetSymbolAddress((void**)&Xb2, g_Xb2);
    cudaGetSymbolAddress((void**)&Xb3, g_Xb3);
    cudaGetSymbolAddress((void**)&X2b, g_X2b);
    cudaGetSymbolAddress((void**)&PL,  g_PL);

    cudaFuncSetAttribute(gemm_bf16, cudaFuncAttributeMaxDynamicSharedMemorySize,
                         GEMM_SMEM_BYTES);
    cudaFuncSetAttribute(gcn_fused, cudaFuncAttributeMaxDynamicSharedMemorySize,
                         GEMM_SMEM_BYTES);

    // prep: convert input to bf16
    prep_kernel<<<1600, 256>>>((const float4*)bin, (uint2*)Xin);

    // encoder L1: (64,25600)@(25600,3200); 12 K-chunks of 2176 -> 300 CTAs
    gemm_bf16<<<dim3(25, 12, 1), 256, GEMM_SMEM_BYTES>>>(Xin, W1, P, 25600, 3200, 2176);
    reduce_act<<<200, 256>>>((const float4*)P, (const float4*)b1, (uint2*)Xb1, 800, 51200, 12, 1);

    // encoder L2: (64,3200)@(3200,6400); 6 K-chunks of 576 -> 300 CTAs
    gemm_bf16<<<dim3(50, 6, 1), 256, GEMM_SMEM_BYTES>>>(Xb1, W2, P, 3200, 6400, 576);
    reduce_act<<<400, 256>>>((const float4*)P, (const float4*)b2, (uint2*)Xb2, 1600, 102400, 6, 1);

    // encoder L3 (no act): (64,6400)@(6400,12800); 3 K-chunks of 2176 -> 300 CTAs
    gemm_bf16<<<dim3(100, 3, 1), 256, GEMM_SMEM_BYTES>>>(Xb2, W3, P, 6400, 12800, 2176);
    reduce_act<<<800, 256>>>((const float4*)P, (const float4*)b3, (uint2*)Xb3, 3200, 204800, 3, 0);

    // GCN L1 fused: H = nodes(50,256)@Wc1 + aggregate -> X2b (per-sample CTA)
    gcn_fused<<<64, 256, GEMM_SMEM_BYTES>>>(Xb3, Wc1, ei, bc1, X2b, nullptr, 256);

    // GCN L2 fused: H = X2(50,128)@Wc2 + aggregate + pool -> PL
    gcn_fused<<<64, 256, GEMM_SMEM_BYTES>>>(X2b, Wc2, ei, bc2, nullptr, PL, 128);

    head_kernel<<<64, 256>>>(PL, Wf1, bf1, Wf2, bf2, out);
}